// round 16
// baseline (speedup 1.0000x reference)
#include <cuda_runtime.h>
#include <cuda_fp16.h>
#include <cstdint>

#define B_ 256
#define S_ 512
#define H_ 512
#define V_ 50257
#define VP_ 50304
#define EPS_ 1e-40f
#define SKRH 40        // halfs per smem row (32 data + 8 pad)
#define NKT 16
#define NPART 1572     // 393 n-tiles * 4 warp col-blocks

__device__ __half g_logith[(size_t)B_ * VP_];
__device__ __half g_Wh[(size_t)V_ * H_];
__device__ __half g_xh[B_ * H_];
__device__ float g_ctx_part[8 * B_ * 1024];
__device__ float g_part_m[(size_t)B_ * NPART];
__device__ float g_part_s[(size_t)B_ * NPART];
__device__ float g_row_M[B_];
__device__ float g_row_S[B_];
__device__ float g_pgen[B_];

static __device__ __forceinline__ uint32_t smem_u32(const void* p) {
    uint32_t r;
    asm("{ .reg .u64 t; cvta.to.shared.u64 t, %1; cvt.u32.u64 %0, t; }" : "=r"(r) : "l"(p));
    return r;
}
static __device__ __forceinline__ void cp16(uint32_t dst, const void* src) {
    asm volatile("cp.async.cg.shared.global [%0], [%1], 16;"
                 :: "r"(dst), "l"(src) : "memory");
}
#define CP_COMMIT() asm volatile("cp.async.commit_group;" ::: "memory")
#define CP_WAIT(n)  asm volatile("cp.async.wait_group %0;" ::"n"(n) : "memory")

static __device__ __forceinline__ void mma16(float* c, const uint32_t* a, uint32_t b0, uint32_t b1) {
    asm volatile(
        "mma.sync.aligned.m16n8k16.row.col.f32.f16.f16.f32 "
        "{%0,%1,%2,%3},{%4,%5,%6,%7},{%8,%9},{%0,%1,%2,%3};"
        : "+f"(c[0]), "+f"(c[1]), "+f"(c[2]), "+f"(c[3])
        : "r"(a[0]), "r"(a[1]), "r"(a[2]), "r"(a[3]), "r"(b0), "r"(b1));
}
#define LDSM4(r0, r1, r2, r3, addr) \
    asm volatile("ldmatrix.sync.aligned.m8n8.x4.shared.b16 {%0,%1,%2,%3}, [%4];" \
                 : "=r"(r0), "=r"(r1), "=r"(r2), "=r"(r3) : "r"(addr))

// ---- K0: fp32 -> fp16 conversion of W and x ----
__global__ void __launch_bounds__(256) k_conv(const float* __restrict__ W,
                                              const float* __restrict__ x) {
    const size_t NW4 = (size_t)V_ * H_ / 4;
    const size_t NX4 = (size_t)B_ * H_ / 4;
    size_t i = (size_t)blockIdx.x * 256 + threadIdx.x;
    if (i < NW4) {
        float4 f = reinterpret_cast<const float4*>(W)[i];
        __half2 h0 = __floats2half2_rn(f.x, f.y);
        __half2 h1 = __floats2half2_rn(f.z, f.w);
        uint2 u = make_uint2(*(uint32_t*)&h0, *(uint32_t*)&h1);
        reinterpret_cast<uint2*>(g_Wh)[i] = u;
    } else if (i < NW4 + NX4) {
        size_t j = i - NW4;
        float4 f = reinterpret_cast<const float4*>(x)[j];
        __half2 h0 = __floats2half2_rn(f.x, f.y);
        __half2 h1 = __floats2half2_rn(f.z, f.w);
        uint2 u = make_uint2(*(uint32_t*)&h0, *(uint32_t*)&h1);
        reinterpret_cast<uint2*>(g_xh)[j] = u;
    }
}

// ---- K1: context partials  ctx[b,h] = sum_s attn[b,s]*enc[s,b,h], S split 8 ----
__global__ void __launch_bounds__(256) k_ctx(const float* __restrict__ enc,
                                             const float* __restrict__ attn) {
    const int b = blockIdx.x, split = blockIdx.y, tid = threadIdx.x;
    __shared__ float sa[64];
    const int s0 = split * 64;
    if (tid < 64) sa[tid] = attn[b * S_ + s0 + tid];
    __syncthreads();
    const float4* ep = reinterpret_cast<const float4*>(enc) + ((size_t)s0 * B_ + b) * 256 + tid;
    float4 acc = make_float4(0.f, 0.f, 0.f, 0.f);
#pragma unroll 8
    for (int s = 0; s < 64; s++) {
        float a = sa[s];
        float4 e = ep[(size_t)s * (B_ * 256)];
        acc.x = fmaf(a, e.x, acc.x); acc.y = fmaf(a, e.y, acc.y);
        acc.z = fmaf(a, e.z, acc.z); acc.w = fmaf(a, e.w, acc.w);
    }
    reinterpret_cast<float4*>(g_ctx_part)[((size_t)split * B_ + b) * 256 + tid] = acc;
}

// ---- K2: reduce ctx + p_gen = sigmoid([hid,emb,ctx]·w + b) ----
__global__ void __launch_bounds__(256) k_pgen(const float* __restrict__ hid,
                                              const float* __restrict__ emb,
                                              const float* __restrict__ pw,
                                              const float* __restrict__ pb) {
    const int b = blockIdx.x, tid = threadIdx.x;
    float4 c = make_float4(0.f, 0.f, 0.f, 0.f);
#pragma unroll
    for (int sp = 0; sp < 8; sp++) {
        float4 p = reinterpret_cast<const float4*>(g_ctx_part)[((size_t)sp * B_ + b) * 256 + tid];
        c.x += p.x; c.y += p.y; c.z += p.z; c.w += p.w;
    }
    float4 w = reinterpret_cast<const float4*>(pw + 1024)[tid];
    float loc = c.x * w.x + c.y * w.y + c.z * w.z + c.w * w.w;
    loc += hid[b * H_ + tid] * pw[tid] + hid[b * H_ + tid + 256] * pw[tid + 256];
    loc += emb[b * H_ + tid] * pw[512 + tid] + emb[b * H_ + tid + 256] * pw[512 + tid + 256];
#pragma unroll
    for (int o = 16; o; o >>= 1) loc += __shfl_xor_sync(~0u, loc, o);
    __shared__ float red[8];
    if ((tid & 31) == 0) red[tid >> 5] = loc;
    __syncthreads();
    if (tid == 0) {
        float z = pb[0];
#pragma unroll
        for (int i = 0; i < 8; i++) z += red[i];
        g_pgen[b] = 1.f / (1.f + __expf(-z));
    }
}

// ---- K3: fp16 mma.sync GEMM, CTA 128x128, warp 64x32, 5-stage, ldmatrix frags ----
#define STGH 10240   // halfs per stage (A 128x40 + B 128x40)
#define NSTG 5
__global__ void __launch_bounds__(256, 2) k_gemm(const float* __restrict__ bias) {
    extern __shared__ __half smh[];
    const int tid = threadIdx.x, lane = tid & 31, wid = tid >> 5;
    const int bm0 = blockIdx.x * 128, bn0 = blockIdx.y * 128;
    const int wm = (wid & 1) * 64, wn = (wid >> 1) * 32;

    float acc[4][4][4];
#pragma unroll
    for (int i = 0; i < 4; i++)
#pragma unroll
        for (int j = 0; j < 4; j++)
#pragma unroll
            for (int r = 0; r < 4; r++) acc[i][j][r] = 0.f;

    auto g2s = [&](int st, int kt) {
        __half* As = smh + st * STGH;
        __half* Bs = As + 128 * SKRH;
        const __half* Ag = g_xh + kt * 32;
        const __half* Wg = g_Wh + kt * 32;
        {
            int idx = tid;
            int r = idx >> 2, q = (idx & 3) << 3;
            cp16(smem_u32(&As[r * SKRH + q]), Ag + (size_t)(bm0 + r) * H_ + q);
            idx = tid + 256;
            r = idx >> 2; q = (idx & 3) << 3;
            cp16(smem_u32(&As[r * SKRH + q]), Ag + (size_t)(bm0 + r) * H_ + q);
        }
        {
            int idx = tid;
            int r = idx >> 2, q = (idx & 3) << 3;
            int n = bn0 + r;
            int nn = (n < V_) ? n : (V_ - 1);
            cp16(smem_u32(&Bs[r * SKRH + q]), Wg + (size_t)nn * H_ + q);
            idx = tid + 256;
            r = idx >> 2; q = (idx & 3) << 3;
            n = bn0 + r;
            nn = (n < V_) ? n : (V_ - 1);
            cp16(smem_u32(&Bs[r * SKRH + q]), Wg + (size_t)nn * H_ + q);
        }
        CP_COMMIT();
    };

    const uint32_t a_off = (uint32_t)(((wm + (lane & 15)) * SKRH + ((lane >> 4) << 3)) * 2);
    const uint32_t b_off = (uint32_t)(((wn + (((lane >> 4) & 1) << 3) + (lane & 7)) * SKRH
                                       + (((lane >> 3) & 1) << 3)) * 2);
    const uint32_t smbase = smem_u32(smh);

    g2s(0, 0); g2s(1, 1); g2s(2, 2); g2s(3, 3);
    for (int kt = 0; kt < NKT; kt++) {
        if (kt < NKT - 3)        CP_WAIT(3);
        else if (kt == NKT - 3)  CP_WAIT(2);
        else if (kt == NKT - 2)  CP_WAIT(1);
        else                     CP_WAIT(0);
        __syncthreads();
        const int st = kt % NSTG;
        const uint32_t As_u = smbase + st * STGH * 2;
        const uint32_t Bs_u = As_u + 128 * SKRH * 2;
#pragma unroll
        for (int ks = 0; ks < 2; ks++) {
            const uint32_t kb = ks * 32;
            uint32_t a[4][4], b[4][2];
#pragma unroll
            for (int mi = 0; mi < 4; mi++)
                LDSM4(a[mi][0], a[mi][1], a[mi][2], a[mi][3],
                      As_u + a_off + mi * 16 * SKRH * 2 + kb);
#pragma unroll
            for (int p = 0; p < 2; p++)
                LDSM4(b[2 * p][0], b[2 * p][1], b[2 * p + 1][0], b[2 * p + 1][1],
                      Bs_u + b_off + p * 16 * SKRH * 2 + kb);
#pragma unroll
            for (int ni = 0; ni < 4; ni++)
#pragma unroll
                for (int mi = 0; mi < 4; mi++)
                    mma16(acc[mi][ni], a[mi], b[ni][0], b[ni][1]);
        }
        if (kt + 4 < NKT) g2s((kt + 4) % NSTG, kt + 4);
    }

    __syncthreads();
    float* sbias = (float*)smh;
    if (tid < 128) {
        int n = bn0 + tid;
        sbias[tid] = (n < V_) ? bias[n] : 0.f;
    }
    __syncthreads();

    float pm[8], ps[8];
#pragma unroll
    for (int r = 0; r < 8; r++) { pm[r] = -1e30f; ps[r] = 0.f; }

#pragma unroll
    for (int mi = 0; mi < 4; mi++) {
        const int m0 = bm0 + wm + mi * 16 + (lane >> 2);
#pragma unroll
        for (int ni = 0; ni < 4; ni++) {
            const int nc = wn + ni * 8 + ((lane & 3) << 1);
            const int n = bn0 + nc;
            const float b0 = sbias[nc], b1 = sbias[nc + 1];
            float v0 = acc[mi][ni][0] + b0, v1 = acc[mi][ni][1] + b1;
            float v2 = acc[mi][ni][2] + b0, v3 = acc[mi][ni][3] + b1;
            const bool ok0 = (n < V_), ok1 = (n + 1 < V_);
            if (ok1) {
                __half2 h01 = __floats2half2_rn(v0, v1);
                __half2 h23 = __floats2half2_rn(v2, v3);
                *(__half2*)&g_logith[(size_t)m0 * VP_ + n]       = h01;
                *(__half2*)&g_logith[(size_t)(m0 + 8) * VP_ + n] = h23;
            } else if (ok0) {
                g_logith[(size_t)m0 * VP_ + n]       = __float2half(v0);
                g_logith[(size_t)(m0 + 8) * VP_ + n] = __float2half(v2);
            }
            float w0 = ok0 ? v0 : -1e30f, w1 = ok1 ? v1 : -1e30f;
            float w2 = ok0 ? v2 : -1e30f, w3 = ok1 ? v3 : -1e30f;
            int r0 = mi * 2, r1 = mi * 2 + 1;
            float mx = fmaxf(w0, w1);
            float nm = fmaxf(pm[r0], mx);
            ps[r0] = ps[r0] * __expf(pm[r0] - nm) + __expf(w0 - nm) + __expf(w1 - nm);
            pm[r0] = nm;
            mx = fmaxf(w2, w3);
            nm = fmaxf(pm[r1], mx);
            ps[r1] = ps[r1] * __expf(pm[r1] - nm) + __expf(w2 - nm) + __expf(w3 - nm);
            pm[r1] = nm;
        }
    }
#pragma unroll
    for (int off = 1; off <= 2; off <<= 1) {
#pragma unroll
        for (int r = 0; r < 8; r++) {
            float om = __shfl_xor_sync(~0u, pm[r], off);
            float os = __shfl_xor_sync(~0u, ps[r], off);
            float nm = fmaxf(pm[r], om);
            ps[r] = ps[r] * __expf(pm[r] - nm) + os * __expf(om - nm);
            pm[r] = nm;
        }
    }
    if ((lane & 3) == 0) {
        const int pidx = blockIdx.y * 4 + (wid >> 1);
#pragma unroll
        for (int r = 0; r < 8; r++) {
            int m = bm0 + wm + (r >> 1) * 16 + (r & 1) * 8 + (lane >> 2);
            g_part_m[(size_t)m * NPART + pidx] = pm[r];
            g_part_s[(size_t)m * NPART + pidx] = ps[r];
        }
    }
}

// ---- K4: reduce softmax partials ----
__global__ void __launch_bounds__(256) k_stats() {
    const int b = blockIdx.x, tid = threadIdx.x;
    float m = -1e30f, s = 0.f;
    for (int i = tid; i < NPART; i += 256) {
        float pm = g_part_m[(size_t)b * NPART + i], pv = g_part_s[(size_t)b * NPART + i];
        float nm = fmaxf(m, pm);
        s = s * __expf(m - nm) + pv * __expf(pm - nm);
        m = nm;
    }
#pragma unroll
    for (int o = 16; o; o >>= 1) {
        float m2 = __shfl_xor_sync(~0u, m, o), s2 = __shfl_xor_sync(~0u, s, o);
        float nm = fmaxf(m, m2);
        s = s * __expf(m - nm) + s2 * __expf(m2 - nm); m = nm;
    }
    __shared__ float sm_[8], ss_[8];
    if ((tid & 31) == 0) { sm_[tid >> 5] = m; ss_[tid >> 5] = s; }
    __syncthreads();
    if (tid == 0) {
        m = sm_[0]; s = ss_[0];
#pragma unroll
        for (int i = 1; i < 8; i++) {
            float nm = fmaxf(m, sm_[i]);
            s = s * __expf(m - nm) + ss_[i] * __expf(sm_[i] - nm); m = nm;
        }
        g_row_M[b] = m; g_row_S[b] = s;
    }
}

// ---- K5: combine+scatter+log. Closed form log(pg*softmax) = C + (l - M) on the
//      no-hit fast path (eps negligible: p >= pg*invS*exp(l-M) >> 1e-40);
//      exp/log only on bitmap hits (~1% of elements). ----
__global__ void __launch_bounds__(512) k_final(const int* __restrict__ ids32,
                                               const float* __restrict__ attn,
                                               float* __restrict__ out) {
    const int b = blockIdx.x, tid = threadIdx.x;
    __shared__ uint32_t bm[VP_ / 32];
    __shared__ int hkey[1024];
    __shared__ float hval[1024];
    for (int i = tid; i < VP_ / 32; i += 512) bm[i] = 0u;
    if (tid < 512) { hkey[tid] = -1; hval[tid] = 0.f;
                     hkey[tid + 512] = -1; hval[tid + 512] = 0.f; }
    const float pg = g_pgen[b];
    __syncthreads();
    {
        int id = ids32[(size_t)b * S_ + tid];
        float pv = (1.f - pg) * attn[b * S_ + tid];
        atomicOr(&bm[id >> 5], 1u << (id & 31));
        uint32_t j = ((uint32_t)id * 0x9E3779B1u) >> 22;
        while (true) {
            int old = atomicCAS(&hkey[j], -1, id);
            if (old == -1 || old == id) { atomicAdd(&hval[j], pv); break; }
            j = (j + 1) & 1023;
        }
    }
    __syncthreads();
    const float M = g_row_M[b];
    const float invS = 1.f / g_row_S[b];
    const float pgS = pg * invS;
    const float C = __logf(pgS);
    const int v0 = blockIdx.y * 12576;
    const int v1 = (v0 + 12576 < V_) ? v0 + 12576 : V_;
    const __half* lrow = g_logith + (size_t)b * VP_;
    float* orow = out + (size_t)b * V_;
    for (int v = v0 + tid; v < v1; v += 512) {
        float l = __half2float(lrow[v]) - M;
        float r;
        if ((bm[v >> 5] >> (v & 31)) & 1u) {
            uint32_t j = ((uint32_t)v * 0x9E3779B1u) >> 22;
            while (hkey[j] != v) j = (j + 1) & 1023;
            r = __logf(pgS * __expf(l) + hval[j] + EPS_);
        } else {
            r = C + l;
        }
        orow[v] = r;
    }
}

extern "C" void kernel_launch(void* const* d_in, const int* in_sizes, int n_in,
                              void* d_out, int out_size) {
    const float* x    = (const float*)d_in[0];
    const float* emb  = (const float*)d_in[1];
    const float* hid  = (const float*)d_in[2];
    const float* enc  = (const float*)d_in[3];
    const float* attn = (const float*)d_in[4];
    const int*   ids  = (const int*)d_in[5];
    const float* pw   = (const float*)d_in[6];
    const float* pb   = (const float*)d_in[7];
    const float* gw   = (const float*)d_in[8];
    const float* gb   = (const float*)d_in[9];
    float* out = (float*)d_out;

    const int smem_gemm = NSTG * STGH * 2;   // 102400 B (5 stages)
    cudaFuncSetAttribute(k_gemm, cudaFuncAttributeMaxDynamicSharedMemorySize, smem_gemm);

    const size_t nconv = ((size_t)V_ * H_ + (size_t)B_ * H_) / 4;
    k_conv <<<(unsigned)((nconv + 255) / 256), 256>>>(pw, x);
    k_ctx  <<<dim3(B_, 8), 256>>>(enc, attn);
    k_pgen <<<B_, 256>>>(hid, emb, gw, gb);
    k_gemm <<<dim3(2, 393), 256, smem_gemm>>>(pb);
    k_stats<<<B_, 256>>>();
    k_final<<<dim3(B_, 4), 512>>>(ids, attn, out);
}

// round 17
// speedup vs baseline: 1.0602x; 1.0602x over previous
#include <cuda_runtime.h>
#include <cuda_fp16.h>
#include <cstdint>

#define B_ 256
#define S_ 512
#define H_ 512
#define V_ 50257
#define VP_ 50304
#define EPS_ 1e-40f
#define SKRH 40        // halfs per smem row (32 data + 8 pad)
#define NKT 16
#define NPART 1572     // 393 n-tiles * 4 warp col-blocks

__device__ __half g_logith[(size_t)B_ * VP_];
__device__ __half g_Wh[(size_t)V_ * H_];
__device__ __half g_xh[B_ * H_];
__device__ float g_ctx_part[8 * B_ * 1024];
__device__ float g_part_m[(size_t)B_ * NPART];
__device__ float g_part_s[(size_t)B_ * NPART];
__device__ float g_row_M[B_];
__device__ float g_row_S[B_];
__device__ float g_pgen[B_];

static __device__ __forceinline__ uint32_t smem_u32(const void* p) {
    uint32_t r;
    asm("{ .reg .u64 t; cvta.to.shared.u64 t, %1; cvt.u32.u64 %0, t; }" : "=r"(r) : "l"(p));
    return r;
}
static __device__ __forceinline__ void cp16(uint32_t dst, const void* src) {
    asm volatile("cp.async.cg.shared.global [%0], [%1], 16;"
                 :: "r"(dst), "l"(src) : "memory");
}
#define CP_COMMIT() asm volatile("cp.async.commit_group;" ::: "memory")
#define CP_WAIT(n)  asm volatile("cp.async.wait_group %0;" ::"n"(n) : "memory")

static __device__ __forceinline__ void mma16(float* c, const uint32_t* a, uint32_t b0, uint32_t b1) {
    asm volatile(
        "mma.sync.aligned.m16n8k16.row.col.f32.f16.f16.f32 "
        "{%0,%1,%2,%3},{%4,%5,%6,%7},{%8,%9},{%0,%1,%2,%3};"
        : "+f"(c[0]), "+f"(c[1]), "+f"(c[2]), "+f"(c[3])
        : "r"(a[0]), "r"(a[1]), "r"(a[2]), "r"(a[3]), "r"(b0), "r"(b1));
}
#define LDSM4(r0, r1, r2, r3, addr) \
    asm volatile("ldmatrix.sync.aligned.m8n8.x4.shared.b16 {%0,%1,%2,%3}, [%4];" \
                 : "=r"(r0), "=r"(r1), "=r"(r2), "=r"(r3) : "r"(addr))

// ---- K0: fp32 -> fp16 conversion of W and x ----
__global__ void __launch_bounds__(256) k_conv(const float* __restrict__ W,
                                              const float* __restrict__ x) {
    const size_t NW4 = (size_t)V_ * H_ / 4;
    const size_t NX4 = (size_t)B_ * H_ / 4;
    size_t i = (size_t)blockIdx.x * 256 + threadIdx.x;
    if (i < NW4) {
        float4 f = reinterpret_cast<const float4*>(W)[i];
        __half2 h0 = __floats2half2_rn(f.x, f.y);
        __half2 h1 = __floats2half2_rn(f.z, f.w);
        uint2 u = make_uint2(*(uint32_t*)&h0, *(uint32_t*)&h1);
        reinterpret_cast<uint2*>(g_Wh)[i] = u;
    } else if (i < NW4 + NX4) {
        size_t j = i - NW4;
        float4 f = reinterpret_cast<const float4*>(x)[j];
        __half2 h0 = __floats2half2_rn(f.x, f.y);
        __half2 h1 = __floats2half2_rn(f.z, f.w);
        uint2 u = make_uint2(*(uint32_t*)&h0, *(uint32_t*)&h1);
        reinterpret_cast<uint2*>(g_xh)[j] = u;
    }
}

// ---- K1: context partials  ctx[b,h] = sum_s attn[b,s]*enc[s,b,h], S split 8 ----
__global__ void __launch_bounds__(256) k_ctx(const float* __restrict__ enc,
                                             const float* __restrict__ attn) {
    const int b = blockIdx.x, split = blockIdx.y, tid = threadIdx.x;
    __shared__ float sa[64];
    const int s0 = split * 64;
    if (tid < 64) sa[tid] = attn[b * S_ + s0 + tid];
    __syncthreads();
    const float4* ep = reinterpret_cast<const float4*>(enc) + ((size_t)s0 * B_ + b) * 256 + tid;
    float4 acc = make_float4(0.f, 0.f, 0.f, 0.f);
#pragma unroll 8
    for (int s = 0; s < 64; s++) {
        float a = sa[s];
        float4 e = ep[(size_t)s * (B_ * 256)];
        acc.x = fmaf(a, e.x, acc.x); acc.y = fmaf(a, e.y, acc.y);
        acc.z = fmaf(a, e.z, acc.z); acc.w = fmaf(a, e.w, acc.w);
    }
    reinterpret_cast<float4*>(g_ctx_part)[((size_t)split * B_ + b) * 256 + tid] = acc;
}

// ---- K2: reduce ctx + p_gen = sigmoid([hid,emb,ctx]·w + b) ----
__global__ void __launch_bounds__(256) k_pgen(const float* __restrict__ hid,
                                              const float* __restrict__ emb,
                                              const float* __restrict__ pw,
                                              const float* __restrict__ pb) {
    const int b = blockIdx.x, tid = threadIdx.x;
    float4 c = make_float4(0.f, 0.f, 0.f, 0.f);
#pragma unroll
    for (int sp = 0; sp < 8; sp++) {
        float4 p = reinterpret_cast<const float4*>(g_ctx_part)[((size_t)sp * B_ + b) * 256 + tid];
        c.x += p.x; c.y += p.y; c.z += p.z; c.w += p.w;
    }
    float4 w = reinterpret_cast<const float4*>(pw + 1024)[tid];
    float loc = c.x * w.x + c.y * w.y + c.z * w.z + c.w * w.w;
    loc += hid[b * H_ + tid] * pw[tid] + hid[b * H_ + tid + 256] * pw[tid + 256];
    loc += emb[b * H_ + tid] * pw[512 + tid] + emb[b * H_ + tid + 256] * pw[512 + tid + 256];
#pragma unroll
    for (int o = 16; o; o >>= 1) loc += __shfl_xor_sync(~0u, loc, o);
    __shared__ float red[8];
    if ((tid & 31) == 0) red[tid >> 5] = loc;
    __syncthreads();
    if (tid == 0) {
        float z = pb[0];
#pragma unroll
        for (int i = 0; i < 8; i++) z += red[i];
        g_pgen[b] = 1.f / (1.f + __expf(-z));
    }
}

// ---- K3: fp16 mma.sync GEMM, CTA 128x128, warp 64x32, 5-stage, ldmatrix frags ----
#define STGH 10240   // halfs per stage (A 128x40 + B 128x40)
#define NSTG 5
__global__ void __launch_bounds__(256, 2) k_gemm(const float* __restrict__ bias) {
    extern __shared__ __half smh[];
    const int tid = threadIdx.x, lane = tid & 31, wid = tid >> 5;
    const int bm0 = blockIdx.x * 128, bn0 = blockIdx.y * 128;
    const int wm = (wid & 1) * 64, wn = (wid >> 1) * 32;

    float acc[4][4][4];
#pragma unroll
    for (int i = 0; i < 4; i++)
#pragma unroll
        for (int j = 0; j < 4; j++)
#pragma unroll
            for (int r = 0; r < 4; r++) acc[i][j][r] = 0.f;

    auto g2s = [&](int st, int kt) {
        __half* As = smh + st * STGH;
        __half* Bs = As + 128 * SKRH;
        const __half* Ag = g_xh + kt * 32;
        const __half* Wg = g_Wh + kt * 32;
        {
            int idx = tid;
            int r = idx >> 2, q = (idx & 3) << 3;
            cp16(smem_u32(&As[r * SKRH + q]), Ag + (size_t)(bm0 + r) * H_ + q);
            idx = tid + 256;
            r = idx >> 2; q = (idx & 3) << 3;
            cp16(smem_u32(&As[r * SKRH + q]), Ag + (size_t)(bm0 + r) * H_ + q);
        }
        {
            int idx = tid;
            int r = idx >> 2, q = (idx & 3) << 3;
            int n = bn0 + r;
            int nn = (n < V_) ? n : (V_ - 1);
            cp16(smem_u32(&Bs[r * SKRH + q]), Wg + (size_t)nn * H_ + q);
            idx = tid + 256;
            r = idx >> 2; q = (idx & 3) << 3;
            n = bn0 + r;
            nn = (n < V_) ? n : (V_ - 1);
            cp16(smem_u32(&Bs[r * SKRH + q]), Wg + (size_t)nn * H_ + q);
        }
        CP_COMMIT();
    };

    const uint32_t a_off = (uint32_t)(((wm + (lane & 15)) * SKRH + ((lane >> 4) << 3)) * 2);
    const uint32_t b_off = (uint32_t)(((wn + (((lane >> 4) & 1) << 3) + (lane & 7)) * SKRH
                                       + (((lane >> 3) & 1) << 3)) * 2);
    const uint32_t smbase = smem_u32(smh);

    g2s(0, 0); g2s(1, 1); g2s(2, 2); g2s(3, 3);
    for (int kt = 0; kt < NKT; kt++) {
        if (kt < NKT - 3)        CP_WAIT(3);
        else if (kt == NKT - 3)  CP_WAIT(2);
        else if (kt == NKT - 2)  CP_WAIT(1);
        else                     CP_WAIT(0);
        __syncthreads();
        const int st = kt % NSTG;
        const uint32_t As_u = smbase + st * STGH * 2;
        const uint32_t Bs_u = As_u + 128 * SKRH * 2;
#pragma unroll
        for (int ks = 0; ks < 2; ks++) {
            const uint32_t kb = ks * 32;
            uint32_t a[4][4], b[4][2];
#pragma unroll
            for (int mi = 0; mi < 4; mi++)
                LDSM4(a[mi][0], a[mi][1], a[mi][2], a[mi][3],
                      As_u + a_off + mi * 16 * SKRH * 2 + kb);
#pragma unroll
            for (int p = 0; p < 2; p++)
                LDSM4(b[2 * p][0], b[2 * p][1], b[2 * p + 1][0], b[2 * p + 1][1],
                      Bs_u + b_off + p * 16 * SKRH * 2 + kb);
#pragma unroll
            for (int ni = 0; ni < 4; ni++)
#pragma unroll
                for (int mi = 0; mi < 4; mi++)
                    mma16(acc[mi][ni], a[mi], b[ni][0], b[ni][1]);
        }
        if (kt + 4 < NKT) g2s((kt + 4) % NSTG, kt + 4);
    }

    __syncthreads();
    float* sbias = (float*)smh;
    if (tid < 128) {
        int n = bn0 + tid;
        sbias[tid] = (n < V_) ? bias[n] : 0.f;
    }
    __syncthreads();

    float pm[8], ps[8];
#pragma unroll
    for (int r = 0; r < 8; r++) { pm[r] = -1e30f; ps[r] = 0.f; }

#pragma unroll
    for (int mi = 0; mi < 4; mi++) {
        const int m0 = bm0 + wm + mi * 16 + (lane >> 2);
#pragma unroll
        for (int ni = 0; ni < 4; ni++) {
            const int nc = wn + ni * 8 + ((lane & 3) << 1);
            const int n = bn0 + nc;
            const float b0 = sbias[nc], b1 = sbias[nc + 1];
            float v0 = acc[mi][ni][0] + b0, v1 = acc[mi][ni][1] + b1;
            float v2 = acc[mi][ni][2] + b0, v3 = acc[mi][ni][3] + b1;
            const bool ok0 = (n < V_), ok1 = (n + 1 < V_);
            if (ok1) {
                __half2 h01 = __floats2half2_rn(v0, v1);
                __half2 h23 = __floats2half2_rn(v2, v3);
                *(__half2*)&g_logith[(size_t)m0 * VP_ + n]       = h01;
                *(__half2*)&g_logith[(size_t)(m0 + 8) * VP_ + n] = h23;
            } else if (ok0) {
                g_logith[(size_t)m0 * VP_ + n]       = __float2half(v0);
                g_logith[(size_t)(m0 + 8) * VP_ + n] = __float2half(v2);
            }
            float w0 = ok0 ? v0 : -1e30f, w1 = ok1 ? v1 : -1e30f;
            float w2 = ok0 ? v2 : -1e30f, w3 = ok1 ? v3 : -1e30f;
            int r0 = mi * 2, r1 = mi * 2 + 1;
            float mx = fmaxf(w0, w1);
            float nm = fmaxf(pm[r0], mx);
            ps[r0] = ps[r0] * __expf(pm[r0] - nm) + __expf(w0 - nm) + __expf(w1 - nm);
            pm[r0] = nm;
            mx = fmaxf(w2, w3);
            nm = fmaxf(pm[r1], mx);
            ps[r1] = ps[r1] * __expf(pm[r1] - nm) + __expf(w2 - nm) + __expf(w3 - nm);
            pm[r1] = nm;
        }
    }
#pragma unroll
    for (int off = 1; off <= 2; off <<= 1) {
#pragma unroll
        for (int r = 0; r < 8; r++) {
            float om = __shfl_xor_sync(~0u, pm[r], off);
            float os = __shfl_xor_sync(~0u, ps[r], off);
            float nm = fmaxf(pm[r], om);
            ps[r] = ps[r] * __expf(pm[r] - nm) + os * __expf(om - nm);
            pm[r] = nm;
        }
    }
    if ((lane & 3) == 0) {
        const int pidx = blockIdx.y * 4 + (wid >> 1);
#pragma unroll
        for (int r = 0; r < 8; r++) {
            int m = bm0 + wm + (r >> 1) * 16 + (r & 1) * 8 + (lane >> 2);
            g_part_m[(size_t)m * NPART + pidx] = pm[r];
            g_part_s[(size_t)m * NPART + pidx] = ps[r];
        }
    }
}

// ---- K4: reduce softmax partials ----
__global__ void __launch_bounds__(256) k_stats() {
    const int b = blockIdx.x, tid = threadIdx.x;
    float m = -1e30f, s = 0.f;
    for (int i = tid; i < NPART; i += 256) {
        float pm = g_part_m[(size_t)b * NPART + i], pv = g_part_s[(size_t)b * NPART + i];
        float nm = fmaxf(m, pm);
        s = s * __expf(m - nm) + pv * __expf(pm - nm);
        m = nm;
    }
#pragma unroll
    for (int o = 16; o; o >>= 1) {
        float m2 = __shfl_xor_sync(~0u, m, o), s2 = __shfl_xor_sync(~0u, s, o);
        float nm = fmaxf(m, m2);
        s = s * __expf(m - nm) + s2 * __expf(m2 - nm); m = nm;
    }
    __shared__ float sm_[8], ss_[8];
    if ((tid & 31) == 0) { sm_[tid >> 5] = m; ss_[tid >> 5] = s; }
    __syncthreads();
    if (tid == 0) {
        m = sm_[0]; s = ss_[0];
#pragma unroll
        for (int i = 1; i < 8; i++) {
            float nm = fmaxf(m, sm_[i]);
            s = s * __expf(m - nm) + ss_[i] * __expf(sm_[i] - nm); m = nm;
        }
        g_row_M[b] = m; g_row_S[b] = s;
    }
}

// ---- K5: combine+scatter+log; closed-form fast path, exp/log only on hits ----
__global__ void __launch_bounds__(512) k_final(const int* __restrict__ ids32,
                                               const float* __restrict__ attn,
                                               float* __restrict__ out) {
    const int b = blockIdx.x, tid = threadIdx.x;
    __shared__ uint32_t bm[VP_ / 32];
    __shared__ int hkey[1024];
    __shared__ float hval[1024];
    for (int i = tid; i < VP_ / 32; i += 512) bm[i] = 0u;
    if (tid < 512) { hkey[tid] = -1; hval[tid] = 0.f;
                     hkey[tid + 512] = -1; hval[tid + 512] = 0.f; }
    const float pg = g_pgen[b];
    __syncthreads();
    {
        int id = ids32[(size_t)b * S_ + tid];
        float pv = (1.f - pg) * attn[b * S_ + tid];
        atomicOr(&bm[id >> 5], 1u << (id & 31));
        uint32_t j = ((uint32_t)id * 0x9E3779B1u) >> 22;
        while (true) {
            int old = atomicCAS(&hkey[j], -1, id);
            if (old == -1 || old == id) { atomicAdd(&hval[j], pv); break; }
            j = (j + 1) & 1023;
        }
    }
    __syncthreads();
    const float M = g_row_M[b];
    const float invS = 1.f / g_row_S[b];
    const float pgS = pg * invS;
    const float C = __logf(pgS);
    const int v0 = blockIdx.y * 12576;
    const int v1 = (v0 + 12576 < V_) ? v0 + 12576 : V_;
    const __half* lrow = g_logith + (size_t)b * VP_;
    float* orow = out + (size_t)b * V_;
    for (int v = v0 + tid; v < v1; v += 512) {
        float l = __half2float(lrow[v]) - M;
        float r;
        if ((bm[v >> 5] >> (v & 31)) & 1u) {
            uint32_t j = ((uint32_t)v * 0x9E3779B1u) >> 22;
            while (hkey[j] != v) j = (j + 1) & 1023;
            r = __logf(pgS * __expf(l) + hval[j] + EPS_);
        } else {
            r = C + l;
        }
        orow[v] = r;
    }
}

extern "C" void kernel_launch(void* const* d_in, const int* in_sizes, int n_in,
                              void* d_out, int out_size) {
    const float* x    = (const float*)d_in[0];
    const float* emb  = (const float*)d_in[1];
    const float* hid  = (const float*)d_in[2];
    const float* enc  = (const float*)d_in[3];
    const float* attn = (const float*)d_in[4];
    const int*   ids  = (const int*)d_in[5];
    const float* pw   = (const float*)d_in[6];
    const float* pb   = (const float*)d_in[7];
    const float* gw   = (const float*)d_in[8];
    const float* gb   = (const float*)d_in[9];
    float* out = (float*)d_out;

    static cudaStream_t s2 = nullptr;
    static cudaEvent_t ev_fork = nullptr, ev_join = nullptr;
    if (s2 == nullptr) {
        cudaStreamCreateWithFlags(&s2, cudaStreamNonBlocking);
        cudaEventCreateWithFlags(&ev_fork, cudaEventDisableTiming);
        cudaEventCreateWithFlags(&ev_join, cudaEventDisableTiming);
    }

    const int smem_gemm = NSTG * STGH * 2;   // 102400 B (5 stages)
    cudaFuncSetAttribute(k_gemm, cudaFuncAttributeMaxDynamicSharedMemorySize, smem_gemm);

    // Fork: ctx+pgen (HBM stream) concurrent with conv+gemm+stats (tensor chain).
    cudaEventRecord(ev_fork, 0);
    cudaStreamWaitEvent(s2, ev_fork, 0);

    k_ctx  <<<dim3(B_, 8), 256, 0, s2>>>(enc, attn);
    k_pgen <<<B_, 256, 0, s2>>>(hid, emb, gw, gb);

    const size_t nconv = ((size_t)V_ * H_ + (size_t)B_ * H_) / 4;
    k_conv <<<(unsigned)((nconv + 255) / 256), 256>>>(pw, x);
    k_gemm <<<dim3(2, 393), 256, smem_gemm>>>(pb);
    k_stats<<<B_, 256>>>();

    cudaEventRecord(ev_join, s2);
    cudaStreamWaitEvent(0, ev_join, 0);

    k_final<<<dim3(B_, 4), 512>>>(ids, attn, out);
}